// round 3
// baseline (speedup 1.0000x reference)
#include <cuda_runtime.h>

// ---------------------------------------------------------------------------
// Problem constants
// ---------------------------------------------------------------------------
#define MV       16
#define BATCH    2
#define SEQ      2048
#define C_CH     64
#define D_DIM    64
#define H_HEADS  8
#define JQ       (D_DIM * H_HEADS)   // 512
#define ROWS     (BATCH * SEQ)       // 4096
#define KQK      (D_DIM * 8)         // 512   (inner-product feature dim)
#define DVF      (D_DIM * MV)        // 1024  (value feature dim)

__constant__ int c_ip[8] = {0, 2, 3, 4, 8, 9, 10, 14};

// ---------------------------------------------------------------------------
// Device-global scratch (no allocations allowed)
// ---------------------------------------------------------------------------
__device__ float g_Wq[(size_t)JQ * MV * C_CH * MV];     // [8192, 1024]
__device__ float g_Wk[(size_t)D_DIM * MV * C_CH * MV];  // [1024, 1024]
__device__ float g_Wv[(size_t)D_DIM * MV * C_CH * MV];  // [1024, 1024]
__device__ float g_Wo[(size_t)C_CH * MV * JQ * MV];     // [1024, 8192]
__device__ float g_Q [(size_t)ROWS * JQ * MV];          // [4096, 8192]
__device__ float g_K [(size_t)ROWS * D_DIM * MV];       // [4096, 1024]
__device__ float g_V [(size_t)ROWS * D_DIM * MV];       // [4096, 1024]
__device__ float g_qm[(size_t)BATCH * H_HEADS * SEQ * KQK];   // [16, 2048, 512]
__device__ float g_km[(size_t)BATCH * SEQ * KQK];             // [2, 2048, 512]
__device__ float g_S [(size_t)BATCH * H_HEADS * SEQ * SEQ];   // [16, 2048, 2048]
__device__ float g_O [(size_t)BATCH * H_HEADS * SEQ * DVF];   // [16, 2048, 1024]
__device__ float g_OF[(size_t)ROWS * JQ * MV];                // [4096, 8192]

// ---------------------------------------------------------------------------
// Packed f32x2 helpers (ptxas never emits FFMA2 from C++; PTX-only path)
// ---------------------------------------------------------------------------
__device__ __forceinline__ unsigned long long pk2(float v) {
    unsigned long long r;
    asm("mov.b64 %0, {%1, %1};" : "=l"(r) : "f"(v));
    return r;
}
__device__ __forceinline__ void fma2(unsigned long long& d,
                                     unsigned long long a,
                                     unsigned long long b) {
    asm("fma.rn.f32x2 %0, %1, %2, %3;" : "=l"(d) : "l"(a), "l"(b), "l"(d));
}

// ---------------------------------------------------------------------------
// Build folded weight:  W[(j*16+y), (i*16+x)] = sum_b w[j,i,b] * blade[b,x,y]
// One block per (j,i) pair; 256 threads = one (x,y) each.
// ---------------------------------------------------------------------------
__global__ __launch_bounds__(256) void build_w(
    const float* __restrict__ w, const float* __restrict__ blade,
    float* __restrict__ W, int J, int I)
{
    __shared__ float bl[9 * 256];
    for (int t = threadIdx.x; t < 9 * 256; t += 256) bl[t] = blade[t];
    __syncthreads();

    int p = blockIdx.x;
    int j = p / I, i = p % I;
    int t = threadIdx.x;
    int x = t & 15, y = t >> 4;
    const float* wp = w + (size_t)(j * I + i) * 9;
    float acc = 0.f;
#pragma unroll
    for (int b = 0; b < 9; b++)
        acc = fmaf(wp[b], bl[b * 256 + x * 16 + y], acc);
    W[(long long)(j * 16 + y) * (I * 16) + i * 16 + x] = acc;
}

// ---------------------------------------------------------------------------
// GEMM (TN): C[M,N] = A[M,K] * B[N,K]^T    (both row-major, K contiguous)
// 128x128 tile, BK=8, 256 threads, 8x8 accumulators as 8x4 packed f32x2.
// Batched via blockIdx.z; B batch index = z >> bShift (shared K/V per b).
// ---------------------------------------------------------------------------
__global__ __launch_bounds__(256) void gemm_tn(
    const float* __restrict__ A, const float* __restrict__ B,
    float* __restrict__ C, int M, int N, int K,
    long long sA, long long sB, long long sC, int bShift)
{
    int z = blockIdx.z;
    A += (long long)z * sA;
    B += (long long)(z >> bShift) * sB;
    C += (long long)z * sC;

    __shared__ __align__(16) float As[8][128];
    __shared__ __align__(16) float Bs[8][128];

    const int tid = threadIdx.x;
    const int m0 = blockIdx.y * 128, n0 = blockIdx.x * 128;
    const int lr = tid >> 1;          // 0..127
    const int lk = (tid & 1) * 4;     // 0 or 4
    const float* Ap = A + (long long)(m0 + lr) * K + lk;
    const float* Bp = B + (long long)(n0 + lr) * K + lk;
    const int ty = tid >> 4, tx = tid & 15;

    unsigned long long acc[8][4];
#pragma unroll
    for (int i = 0; i < 8; i++)
#pragma unroll
        for (int j = 0; j < 4; j++) acc[i][j] = 0ull;

    for (int k0 = 0; k0 < K; k0 += 8) {
        float4 av = *(const float4*)(Ap + k0);
        float4 bv = *(const float4*)(Bp + k0);
        As[lk + 0][lr] = av.x; As[lk + 1][lr] = av.y;
        As[lk + 2][lr] = av.z; As[lk + 3][lr] = av.w;
        Bs[lk + 0][lr] = bv.x; Bs[lk + 1][lr] = bv.y;
        Bs[lk + 2][lr] = bv.z; Bs[lk + 3][lr] = bv.w;
        __syncthreads();
#pragma unroll
        for (int kk = 0; kk < 8; kk++) {
            float4 a0 = *(const float4*)&As[kk][ty * 8];
            float4 a1 = *(const float4*)&As[kk][ty * 8 + 4];
            ulonglong2 b01 = *(const ulonglong2*)&Bs[kk][tx * 8];
            ulonglong2 b23 = *(const ulonglong2*)&Bs[kk][tx * 8 + 4];
            float a[8] = {a0.x, a0.y, a0.z, a0.w, a1.x, a1.y, a1.z, a1.w};
            unsigned long long bb[4] = {b01.x, b01.y, b23.x, b23.y};
#pragma unroll
            for (int i = 0; i < 8; i++) {
                unsigned long long ai = pk2(a[i]);
#pragma unroll
                for (int j = 0; j < 4; j++) fma2(acc[i][j], ai, bb[j]);
            }
        }
        __syncthreads();
    }

#pragma unroll
    for (int i = 0; i < 8; i++) {
        long long r = (long long)(m0 + ty * 8 + i) * N + n0 + tx * 8;
        *(ulonglong2*)(C + r)     = make_ulonglong2(acc[i][0], acc[i][1]);
        *(ulonglong2*)(C + r + 4) = make_ulonglong2(acc[i][2], acc[i][3]);
    }
}

// ---------------------------------------------------------------------------
// GEMM (NN): C[M,N] = A[M,K] * B[K,N]    (row-major)
// ---------------------------------------------------------------------------
__global__ __launch_bounds__(256) void gemm_nn(
    const float* __restrict__ A, const float* __restrict__ B,
    float* __restrict__ C, int M, int N, int K,
    long long sA, long long sB, long long sC, int bShift)
{
    int z = blockIdx.z;
    A += (long long)z * sA;
    B += (long long)(z >> bShift) * sB;
    C += (long long)z * sC;

    __shared__ __align__(16) float As[8][128];
    __shared__ __align__(16) float Bs[8][128];

    const int tid = threadIdx.x;
    const int m0 = blockIdx.y * 128, n0 = blockIdx.x * 128;
    const int lr = tid >> 1;
    const int lk = (tid & 1) * 4;
    const float* Ap = A + (long long)(m0 + lr) * K + lk;
    const int br = tid >> 5;          // 0..7
    const int bc = (tid & 31) * 4;    // 0..124
    const float* Bp = B + (long long)br * N + n0 + bc;
    const int ty = tid >> 4, tx = tid & 15;

    unsigned long long acc[8][4];
#pragma unroll
    for (int i = 0; i < 8; i++)
#pragma unroll
        for (int j = 0; j < 4; j++) acc[i][j] = 0ull;

    for (int k0 = 0; k0 < K; k0 += 8) {
        float4 av = *(const float4*)(Ap + k0);
        float4 bv = *(const float4*)(Bp + (long long)k0 * N);
        As[lk + 0][lr] = av.x; As[lk + 1][lr] = av.y;
        As[lk + 2][lr] = av.z; As[lk + 3][lr] = av.w;
        *(float4*)&Bs[br][bc] = bv;
        __syncthreads();
#pragma unroll
        for (int kk = 0; kk < 8; kk++) {
            float4 a0 = *(const float4*)&As[kk][ty * 8];
            float4 a1 = *(const float4*)&As[kk][ty * 8 + 4];
            ulonglong2 b01 = *(const ulonglong2*)&Bs[kk][tx * 8];
            ulonglong2 b23 = *(const ulonglong2*)&Bs[kk][tx * 8 + 4];
            float a[8] = {a0.x, a0.y, a0.z, a0.w, a1.x, a1.y, a1.z, a1.w};
            unsigned long long bb[4] = {b01.x, b01.y, b23.x, b23.y};
#pragma unroll
            for (int i = 0; i < 8; i++) {
                unsigned long long ai = pk2(a[i]);
#pragma unroll
                for (int j = 0; j < 4; j++) fma2(acc[i][j], ai, bb[j]);
            }
        }
        __syncthreads();
    }

#pragma unroll
    for (int i = 0; i < 8; i++) {
        long long r = (long long)(m0 + ty * 8 + i) * N + n0 + tx * 8;
        *(ulonglong2*)(C + r)     = make_ulonglong2(acc[i][0], acc[i][1]);
        *(ulonglong2*)(C + r + 4) = make_ulonglong2(acc[i][2], acc[i][3]);
    }
}

// ---------------------------------------------------------------------------
// qm extraction: qm[b,h,n, d*8+e] = scale * Q[b*N+n, (d*8+h)*16 + ip[e]]
// ---------------------------------------------------------------------------
__global__ __launch_bounds__(256) void extract_qm(
    const float* __restrict__ Q, float* __restrict__ qm)
{
    int idx = blockIdx.x * 256 + threadIdx.x;   // total 16,777,216
    int e = idx & 7;
    int d = (idx >> 3) & 63;
    int n = (idx >> 9) & 2047;
    int h = (idx >> 20) & 7;
    int b = idx >> 23;
    const float scale = 0.044194173824159216f;  // 1/sqrt(512)
    qm[idx] = scale * Q[(long long)(b * SEQ + n) * (JQ * MV) + (d * 8 + h) * 16 + c_ip[e]];
}

// km[b,n, d*8+e] = K[b*N+n, d*16 + ip[e]]
__global__ __launch_bounds__(256) void extract_km(
    const float* __restrict__ K, float* __restrict__ km)
{
    int idx = blockIdx.x * 256 + threadIdx.x;   // total 2,097,152
    int e = idx & 7;
    int d = (idx >> 3) & 63;
    int n = (idx >> 9) & 2047;
    int b = idx >> 20;
    km[idx] = K[(long long)(b * SEQ + n) * DVF + d * 16 + c_ip[e]];
}

// ---------------------------------------------------------------------------
// Row softmax over 2048 columns; one block per row, 8 elems per thread.
// ---------------------------------------------------------------------------
__global__ __launch_bounds__(256) void softmax_rows(float* __restrict__ S)
{
    long long row = blockIdx.x;
    float* p = S + row * 2048;
    int t = threadIdx.x;
    float4 a = *(float4*)(p + t * 8);
    float4 c = *(float4*)(p + t * 8 + 4);
    float v[8] = {a.x, a.y, a.z, a.w, c.x, c.y, c.z, c.w};

    __shared__ float redm[8];
    __shared__ float reds[8];
    __shared__ float bcast[2];
    int wid = t >> 5, lane = t & 31;

    float m = v[0];
#pragma unroll
    for (int i = 1; i < 8; i++) m = fmaxf(m, v[i]);
#pragma unroll
    for (int off = 16; off; off >>= 1)
        m = fmaxf(m, __shfl_xor_sync(0xffffffffu, m, off));
    if (lane == 0) redm[wid] = m;
    __syncthreads();
    if (t == 0) {
        float mm = redm[0];
#pragma unroll
        for (int i = 1; i < 8; i++) mm = fmaxf(mm, redm[i]);
        bcast[0] = mm;
    }
    __syncthreads();
    m = bcast[0];

    float s = 0.f;
#pragma unroll
    for (int i = 0; i < 8; i++) { v[i] = expf(v[i] - m); s += v[i]; }
#pragma unroll
    for (int off = 16; off; off >>= 1)
        s += __shfl_xor_sync(0xffffffffu, s, off);
    if (lane == 0) reds[wid] = s;
    __syncthreads();
    if (t == 0) {
        float ss = 0.f;
#pragma unroll
        for (int i = 0; i < 8; i++) ss += reds[i];
        bcast[1] = ss;
    }
    __syncthreads();
    float inv = 1.f / bcast[1];

    *(float4*)(p + t * 8)     = make_float4(v[0] * inv, v[1] * inv, v[2] * inv, v[3] * inv);
    *(float4*)(p + t * 8 + 4) = make_float4(v[4] * inv, v[5] * inv, v[6] * inv, v[7] * inv);
}

// ---------------------------------------------------------------------------
// Reorder attention output [b,h,n, d*16+m] -> flat [b*N+n, (h*64+d)*16+m]
// float4 granularity (fully coalesced).
// ---------------------------------------------------------------------------
__global__ __launch_bounds__(256) void reorder_o(
    const float* __restrict__ O, float* __restrict__ OF)
{
    int idx = blockIdx.x * 256 + threadIdx.x;   // total 8,388,608 float4
    int q4 = idx & 255;
    int n  = (idx >> 8) & 2047;
    int h  = (idx >> 19) & 7;
    int b  = idx >> 22;
    const float4* Ov = (const float4*)O;
    float4* OFv = (float4*)OF;
    OFv[(long long)(b * SEQ + n) * 2048 + h * 256 + q4] =
        Ov[(long long)((b * 8 + h) * SEQ + n) * 256 + q4];
}

// ---------------------------------------------------------------------------
// Host launcher
// ---------------------------------------------------------------------------
extern "C" void kernel_launch(void* const* d_in, const int* in_sizes, int n_in,
                              void* d_out, int out_size)
{
    const float* x     = (const float*)d_in[0];
    const float* blade = (const float*)d_in[1];
    const float* wq    = (const float*)d_in[2];
    const float* wk    = (const float*)d_in[3];
    const float* wv    = (const float*)d_in[4];
    const float* wo    = (const float*)d_in[5];
    float* out = (float*)d_out;

    float *Wq, *Wk, *Wv, *Wo, *Q, *Kb, *Vb, *qm, *km, *S, *O, *OF;
    cudaGetSymbolAddress((void**)&Wq, g_Wq);
    cudaGetSymbolAddress((void**)&Wk, g_Wk);
    cudaGetSymbolAddress((void**)&Wv, g_Wv);
    cudaGetSymbolAddress((void**)&Wo, g_Wo);
    cudaGetSymbolAddress((void**)&Q,  g_Q);
    cudaGetSymbolAddress((void**)&Kb, g_K);
    cudaGetSymbolAddress((void**)&Vb, g_V);
    cudaGetSymbolAddress((void**)&qm, g_qm);
    cudaGetSymbolAddress((void**)&km, g_km);
    cudaGetSymbolAddress((void**)&S,  g_S);
    cudaGetSymbolAddress((void**)&O,  g_O);
    cudaGetSymbolAddress((void**)&OF, g_OF);

    // 1) Fold blade into big weight matrices
    build_w<<<JQ * C_CH, 256>>>(wq, blade, Wq, JQ, C_CH);          // [8192,1024]
    build_w<<<D_DIM * C_CH, 256>>>(wk, blade, Wk, D_DIM, C_CH);    // [1024,1024]
    build_w<<<D_DIM * C_CH, 256>>>(wv, blade, Wv, D_DIM, C_CH);    // [1024,1024]
    build_w<<<C_CH * JQ, 256>>>(wo, blade, Wo, C_CH, JQ);          // [1024,8192]

    // 2) Projections: X[4096,1024] * W^T
    gemm_tn<<<dim3(JQ * MV / 128, ROWS / 128, 1), 256>>>(
        x, Wq, Q, ROWS, JQ * MV, C_CH * MV, 0, 0, 0, 0);
    gemm_tn<<<dim3(DVF / 128, ROWS / 128, 1), 256>>>(
        x, Wk, Kb, ROWS, DVF, C_CH * MV, 0, 0, 0, 0);
    gemm_tn<<<dim3(DVF / 128, ROWS / 128, 1), 256>>>(
        x, Wv, Vb, ROWS, DVF, C_CH * MV, 0, 0, 0, 0);

    // 3) Extract inner-product coordinates (scale folded into qm)
    extract_qm<<<(BATCH * H_HEADS * SEQ * KQK) / 256, 256>>>(Q, qm);
    extract_km<<<(BATCH * SEQ * KQK) / 256, 256>>>(Kb, km);

    // 4) scores[z] = qm[z] @ km[z>>3]^T   (16 batches)
    gemm_tn<<<dim3(SEQ / 128, SEQ / 128, BATCH * H_HEADS), 256>>>(
        qm, km, S, SEQ, SEQ, KQK,
        (long long)SEQ * KQK, (long long)SEQ * KQK, (long long)SEQ * SEQ, 3);

    // 5) softmax over rows
    softmax_rows<<<BATCH * H_HEADS * SEQ, 256>>>(S);

    // 6) O[z] = S[z] @ V[z>>3]
    gemm_nn<<<dim3(DVF / 128, SEQ / 128, BATCH * H_HEADS), 256>>>(
        S, Vb, O, SEQ, DVF, SEQ,
        (long long)SEQ * SEQ, (long long)SEQ * DVF, (long long)SEQ * DVF, 3);

    // 7) head-merge reorder to [4096, 8192]
    reorder_o<<<(BATCH * H_HEADS * SEQ * 256) / 256, 256>>>(O, OF);

    // 8) final projection: OF[4096,8192] * Wo[1024,8192]^T -> out [4096,1024]
    gemm_tn<<<dim3(C_CH * MV / 128, ROWS / 128, 1), 256>>>(
        OF, Wo, out, ROWS, C_CH * MV, JQ * MV, 0, 0, 0, 0);
}

// round 5
// speedup vs baseline: 1.5141x; 1.5141x over previous
#include <cuda_runtime.h>

// ---------------------------------------------------------------------------
// Problem constants
// ---------------------------------------------------------------------------
#define MV       16
#define BATCH    2
#define SEQ      2048
#define C_CH     64
#define D_DIM    64
#define H_HEADS  8
#define JQ       (D_DIM * H_HEADS)   // 512
#define ROWS     (BATCH * SEQ)       // 4096
#define KQK      (D_DIM * 8)         // 512
#define DVF      (D_DIM * MV)        // 1024

__constant__ int c_ip[8] = {0, 2, 3, 4, 8, 9, 10, 14};

// ---------------------------------------------------------------------------
// Device-global scratch (no allocations allowed)
// ---------------------------------------------------------------------------
__device__ float g_Wq[(size_t)JQ * MV * C_CH * MV];     // [8192, 1024]
__device__ float g_Wk[(size_t)D_DIM * MV * C_CH * MV];  // [1024, 1024]
__device__ float g_Wv[(size_t)D_DIM * MV * C_CH * MV];  // [1024, 1024]
__device__ float g_Wo[(size_t)C_CH * MV * JQ * MV];     // [1024, 8192]
__device__ float g_Q [(size_t)ROWS * JQ * MV];          // [4096, 8192]
__device__ float g_K [(size_t)ROWS * D_DIM * MV];       // [4096, 1024]
__device__ float g_V [(size_t)ROWS * D_DIM * MV];       // [4096, 1024]
__device__ float g_qm[(size_t)BATCH * H_HEADS * SEQ * KQK];   // [16, 2048, 512]
__device__ float g_km[(size_t)BATCH * SEQ * KQK];             // [2, 2048, 512]
__device__ float g_S [(size_t)BATCH * H_HEADS * SEQ * SEQ];   // [16, 2048, 2048]
__device__ float g_O [(size_t)BATCH * H_HEADS * SEQ * DVF];   // [16, 2048, 1024]
__device__ float g_OF[(size_t)ROWS * JQ * MV];                // [4096, 8192]

// ---------------------------------------------------------------------------
// Packed f32x2 helpers (ptxas never emits FFMA2 from C++; PTX-only path)
// ---------------------------------------------------------------------------
__device__ __forceinline__ unsigned long long pk2(float v) {
    unsigned long long r;
    asm("mov.b64 %0, {%1, %1};" : "=l"(r) : "f"(v));
    return r;
}
__device__ __forceinline__ void fma2(unsigned long long& d,
                                     unsigned long long a,
                                     unsigned long long b) {
    asm("fma.rn.f32x2 %0, %1, %2, %3;" : "=l"(d) : "l"(a), "l"(b), "l"(d));
}

// ---------------------------------------------------------------------------
// Build folded weight:  W[(j*16+y), (i*16+x)] = sum_b w[j,i,b] * blade[b,x,y]
// ---------------------------------------------------------------------------
__global__ __launch_bounds__(256) void build_w(
    const float* __restrict__ w, const float* __restrict__ blade,
    float* __restrict__ W, int J, int I)
{
    __shared__ float bl[9 * 256];
    for (int t = threadIdx.x; t < 9 * 256; t += 256) bl[t] = blade[t];
    __syncthreads();

    int p = blockIdx.x;
    int j = p / I, i = p % I;
    int t = threadIdx.x;
    int x = t & 15, y = t >> 4;
    const float* wp = w + (size_t)(j * I + i) * 9;
    float acc = 0.f;
#pragma unroll
    for (int b = 0; b < 9; b++)
        acc = fmaf(wp[b], bl[b * 256 + x * 16 + y], acc);
    W[(long long)(j * 16 + y) * (I * 16) + i * 16 + x] = acc;
}

// ---------------------------------------------------------------------------
// GEMM (TN): C[M,N] = A[M,K] * B[N,K]^T  — fp32 with packed FFMA2
// 128x128 tile, BK=8, 256 threads, 8x8 accumulators as 8x4 packed f32x2.
// Batched via blockIdx.z; B batch index = z >> bShift.
// ---------------------------------------------------------------------------
__global__ __launch_bounds__(256) void gemm_tn(
    const float* __restrict__ A, const float* __restrict__ B,
    float* __restrict__ C, int M, int N, int K,
    long long sA, long long sB, long long sC, int bShift)
{
    int z = blockIdx.z;
    A += (long long)z * sA;
    B += (long long)(z >> bShift) * sB;
    C += (long long)z * sC;

    __shared__ __align__(16) float As[8][128];
    __shared__ __align__(16) float Bs[8][128];

    const int tid = threadIdx.x;
    const int m0 = blockIdx.y * 128, n0 = blockIdx.x * 128;
    const int lr = tid >> 1;          // 0..127
    const int lk = (tid & 1) * 4;     // 0 or 4
    const float* Ap = A + (long long)(m0 + lr) * K + lk;
    const float* Bp = B + (long long)(n0 + lr) * K + lk;
    const int ty = tid >> 4, tx = tid & 15;

    unsigned long long acc[8][4];
#pragma unroll
    for (int i = 0; i < 8; i++)
#pragma unroll
        for (int j = 0; j < 4; j++) acc[i][j] = 0ull;

    for (int k0 = 0; k0 < K; k0 += 8) {
        float4 av = *(const float4*)(Ap + k0);
        float4 bv = *(const float4*)(Bp + k0);
        As[lk + 0][lr] = av.x; As[lk + 1][lr] = av.y;
        As[lk + 2][lr] = av.z; As[lk + 3][lr] = av.w;
        Bs[lk + 0][lr] = bv.x; Bs[lk + 1][lr] = bv.y;
        Bs[lk + 2][lr] = bv.z; Bs[lk + 3][lr] = bv.w;
        __syncthreads();
#pragma unroll
        for (int kk = 0; kk < 8; kk++) {
            float4 a0 = *(const float4*)&As[kk][ty * 8];
            float4 a1 = *(const float4*)&As[kk][ty * 8 + 4];
            ulonglong2 b01 = *(const ulonglong2*)&Bs[kk][tx * 8];
            ulonglong2 b23 = *(const ulonglong2*)&Bs[kk][tx * 8 + 4];
            float a[8] = {a0.x, a0.y, a0.z, a0.w, a1.x, a1.y, a1.z, a1.w};
            unsigned long long bb[4] = {b01.x, b01.y, b23.x, b23.y};
#pragma unroll
            for (int i = 0; i < 8; i++) {
                unsigned long long ai = pk2(a[i]);
#pragma unroll
                for (int j = 0; j < 4; j++) fma2(acc[i][j], ai, bb[j]);
            }
        }
        __syncthreads();
    }

#pragma unroll
    for (int i = 0; i < 8; i++) {
        long long r = (long long)(m0 + ty * 8 + i) * N + n0 + tx * 8;
        *(ulonglong2*)(C + r)     = make_ulonglong2(acc[i][0], acc[i][1]);
        *(ulonglong2*)(C + r + 4) = make_ulonglong2(acc[i][2], acc[i][3]);
    }
}

// ---------------------------------------------------------------------------
// qm extraction: qm[b,h,n, d*8+e] = scale * Q[b*N+n, (d*8+h)*16 + ip[e]]
// ---------------------------------------------------------------------------
__global__ __launch_bounds__(256) void extract_qm(
    const float* __restrict__ Q, float* __restrict__ qm)
{
    int idx = blockIdx.x * 256 + threadIdx.x;   // total 16,777,216
    int e = idx & 7;
    int d = (idx >> 3) & 63;
    int n = (idx >> 9) & 2047;
    int h = (idx >> 20) & 7;
    int b = idx >> 23;
    const float scale = 0.044194173824159216f;  // 1/sqrt(512)
    qm[idx] = scale * Q[(long long)(b * SEQ + n) * (JQ * MV) + (d * 8 + h) * 16 + c_ip[e]];
}

// km[b,n, d*8+e] = K[b*N+n, d*16 + ip[e]]
__global__ __launch_bounds__(256) void extract_km(
    const float* __restrict__ K, float* __restrict__ km)
{
    int idx = blockIdx.x * 256 + threadIdx.x;   // total 2,097,152
    int e = idx & 7;
    int d = (idx >> 3) & 63;
    int n = (idx >> 9) & 2047;
    int b = idx >> 20;
    km[idx] = K[(long long)(b * SEQ + n) * DVF + d * 16 + c_ip[e]];
}

// ---------------------------------------------------------------------------
// Fused softmax + sparse AV gather.
// One block per attention row (b,h,q). Exact softmax denominator over all
// 2048 keys; only keys with logit > max-44 contribute to the output
// (exp(-44) ~ 7.8e-20 -> total excluded mass < 2e-16 relative, below fp32
// rounding -> mathematically exact at fp32). With logits ~N(mu, 3000) the
// kept set is typically 1-3 keys, collapsing the 137 GF AV GEMM to a gather.
// Deterministic: kept keys compacted in ascending-k order via prefix scan.
// ---------------------------------------------------------------------------
__global__ __launch_bounds__(256) void softmax_gather(
    const float* __restrict__ S, const float* __restrict__ V,
    float* __restrict__ O)
{
    const long long row = blockIdx.x;           // (b*8+h)*2048 + q
    const int b = (int)(row >> 14);             // row / (8*2048)
    const float* p = S + row * 2048;
    const float* Vb = V + (long long)b * SEQ * DVF;
    float* Orow = O + row * DVF;

    __shared__ float red[8];
    __shared__ float bc[2];
    __shared__ int warp_base[8];
    __shared__ int s_cnt;
    __shared__ int   s_idx[2048];
    __shared__ float s_w[2048];

    const int t = threadIdx.x, wid = t >> 5, lane = t & 31;

    float4 a = *(const float4*)(p + t * 8);
    float4 c = *(const float4*)(p + t * 8 + 4);
    float v[8] = {a.x, a.y, a.z, a.w, c.x, c.y, c.z, c.w};

    // ---- block max ----
    float m = v[0];
#pragma unroll
    for (int i = 1; i < 8; i++) m = fmaxf(m, v[i]);
#pragma unroll
    for (int off = 16; off; off >>= 1)
        m = fmaxf(m, __shfl_xor_sync(0xffffffffu, m, off));
    if (lane == 0) red[wid] = m;
    __syncthreads();
    if (t == 0) {
        float mm = red[0];
#pragma unroll
        for (int i = 1; i < 8; i++) mm = fmaxf(mm, red[i]);
        bc[0] = mm;
    }
    __syncthreads();
    m = bc[0];

    // ---- exp, sum, selection flags ----
    const float thr = m - 44.0f;
    float s = 0.f;
    int sel = 0, cnt_local = 0;
#pragma unroll
    for (int i = 0; i < 8; i++) {
        if (v[i] > thr) { sel |= (1 << i); cnt_local++; }
        v[i] = expf(v[i] - m);
        s += v[i];
    }
#pragma unroll
    for (int off = 16; off; off >>= 1)
        s += __shfl_xor_sync(0xffffffffu, s, off);
    if (lane == 0) red[wid] = s;

    // ---- deterministic compaction: block exclusive prefix of cnt_local ----
    int inc = cnt_local;
#pragma unroll
    for (int off = 1; off < 32; off <<= 1) {
        int nv = __shfl_up_sync(0xffffffffu, inc, off);
        if (lane >= off) inc += nv;
    }
    if (lane == 31) warp_base[wid] = inc;   // warp total
    __syncthreads();
    if (t == 0) {
        float ss = red[0];
#pragma unroll
        for (int i = 1; i < 8; i++) ss += red[i];
        bc[1] = ss;
        int run = 0;
#pragma unroll
        for (int w = 0; w < 8; w++) { int tw = warp_base[w]; warp_base[w] = run; run += tw; }
        s_cnt = run;
    }
    __syncthreads();

    int pos = warp_base[wid] + inc - cnt_local;
#pragma unroll
    for (int i = 0; i < 8; i++) {
        if (sel & (1 << i)) {
            s_idx[pos] = t * 8 + i;
            s_w[pos] = v[i];
            pos++;
        }
    }
    __syncthreads();

    // ---- weighted gather of V rows ----
    const float inv = 1.f / bc[1];
    const int cnt = s_cnt;
    float a0 = 0.f, a1 = 0.f, a2 = 0.f, a3 = 0.f;
    for (int j = 0; j < cnt; j++) {
        const float w = s_w[j] * inv;
        const float4 vv = *(const float4*)(Vb + (long long)s_idx[j] * DVF + t * 4);
        a0 = fmaf(w, vv.x, a0);
        a1 = fmaf(w, vv.y, a1);
        a2 = fmaf(w, vv.z, a2);
        a3 = fmaf(w, vv.w, a3);
    }
    *(float4*)(Orow + t * 4) = make_float4(a0, a1, a2, a3);
}

// ---------------------------------------------------------------------------
// Reorder attention output [b,h,n, d*16+m] -> flat [b*N+n, (h*64+d)*16+m]
// ---------------------------------------------------------------------------
__global__ __launch_bounds__(256) void reorder_o(
    const float* __restrict__ O, float* __restrict__ OF)
{
    int idx = blockIdx.x * 256 + threadIdx.x;   // total 8,388,608 float4
    int q4 = idx & 255;
    int n  = (idx >> 8) & 2047;
    int h  = (idx >> 19) & 7;
    int b  = idx >> 22;
    const float4* Ov = (const float4*)O;
    float4* OFv = (float4*)OF;
    OFv[(long long)(b * SEQ + n) * 2048 + h * 256 + q4] =
        Ov[(long long)((b * 8 + h) * SEQ + n) * 256 + q4];
}

// ---------------------------------------------------------------------------
// Host launcher
// ---------------------------------------------------------------------------
extern "C" void kernel_launch(void* const* d_in, const int* in_sizes, int n_in,
                              void* d_out, int out_size)
{
    const float* x     = (const float*)d_in[0];
    const float* blade = (const float*)d_in[1];
    const float* wq    = (const float*)d_in[2];
    const float* wk    = (const float*)d_in[3];
    const float* wv    = (const float*)d_in[4];
    const float* wo    = (const float*)d_in[5];
    float* out = (float*)d_out;

    float *Wq, *Wk, *Wv, *Wo, *Q, *Kb, *Vb, *qm, *km, *S, *O, *OF;
    cudaGetSymbolAddress((void**)&Wq, g_Wq);
    cudaGetSymbolAddress((void**)&Wk, g_Wk);
    cudaGetSymbolAddress((void**)&Wv, g_Wv);
    cudaGetSymbolAddress((void**)&Wo, g_Wo);
    cudaGetSymbolAddress((void**)&Q,  g_Q);
    cudaGetSymbolAddress((void**)&Kb, g_K);
    cudaGetSymbolAddress((void**)&Vb, g_V);
    cudaGetSymbolAddress((void**)&qm, g_qm);
    cudaGetSymbolAddress((void**)&km, g_km);
    cudaGetSymbolAddress((void**)&S,  g_S);
    cudaGetSymbolAddress((void**)&O,  g_O);
    cudaGetSymbolAddress((void**)&OF, g_OF);

    // 1) Fold blade into big weight matrices
    build_w<<<JQ * C_CH, 256>>>(wq, blade, Wq, JQ, C_CH);          // [8192,1024]
    build_w<<<D_DIM * C_CH, 256>>>(wk, blade, Wk, D_DIM, C_CH);    // [1024,1024]
    build_w<<<D_DIM * C_CH, 256>>>(wv, blade, Wv, D_DIM, C_CH);    // [1024,1024]
    build_w<<<C_CH * JQ, 256>>>(wo, blade, Wo, C_CH, JQ);          // [1024,8192]

    // 2) Projections: X[4096,1024] * W^T
    gemm_tn<<<dim3(JQ * MV / 128, ROWS / 128, 1), 256>>>(
        x, Wq, Q, ROWS, JQ * MV, C_CH * MV, 0, 0, 0, 0);
    gemm_tn<<<dim3(DVF / 128, ROWS / 128, 1), 256>>>(
        x, Wk, Kb, ROWS, DVF, C_CH * MV, 0, 0, 0, 0);
    gemm_tn<<<dim3(DVF / 128, ROWS / 128, 1), 256>>>(
        x, Wv, Vb, ROWS, DVF, C_CH * MV, 0, 0, 0, 0);

    // 3) Extract inner-product coordinates (scale folded into qm)
    extract_qm<<<(BATCH * H_HEADS * SEQ * KQK) / 256, 256>>>(Q, qm);
    extract_km<<<(BATCH * SEQ * KQK) / 256, 256>>>(Kb, km);

    // 4) scores[z] = qm[z] @ km[z>>3]^T   (16 batches)
    gemm_tn<<<dim3(SEQ / 128, SEQ / 128, BATCH * H_HEADS), 256>>>(
        qm, km, S, SEQ, SEQ, KQK,
        (long long)SEQ * KQK, (long long)SEQ * KQK, (long long)SEQ * SEQ, 3);

    // 5) fused softmax + sparse AV (replaces softmax pass + 137 GF AV GEMM)
    softmax_gather<<<BATCH * H_HEADS * SEQ, 256>>>(S, Vb, O);

    // 6) head-merge reorder to [4096, 8192]
    reorder_o<<<(BATCH * H_HEADS * SEQ * 256) / 256, 256>>>(O, OF);

    // 7) final projection: OF[4096,8192] * Wo[1024,8192]^T -> out [4096,1024]
    gemm_tn<<<dim3(C_CH * MV / 128, ROWS / 128, 1), 256>>>(
        OF, Wo, out, ROWS, C_CH * MV, JQ * MV, 0, 0, 0, 0);
}